// round 10
// baseline (speedup 1.0000x reference)
#include <cuda_runtime.h>
#include <math.h>

#define BB 16
#define LATD 8
#define NPTS 500000
#define XSZ 256
#define HSPEC 129   // XSZ/2 + 1
#define IMG_ELEMS (BB*XSZ*XSZ)
#define ZERO_BLKS (IMG_ELEMS/4/256)   // 1024 float4-zero blocks

// ---------------- scratch (device globals; no allocation allowed) ----------
__device__ float  g_img[IMG_ELEMS];                  // 4 MB accumulation image
__device__ float2 g_spec[BB*HSPEC*XSZ];              // spectrum, layout [b][kx][y]
__device__ float  g_ctft[BB*HSPEC*XSZ];              // ctf transposed [b][kx][ky]
__device__ float  g_params[BB][16];                  // R rows(6), shifts(2), h(8)
__device__ float2 g_tw[128];                         // exp(-2*pi*i*k/256)

// Gaussian kernel (sigma=1, radius=3), normalized (double-derived constants)
__device__ __constant__ float c_gk[7] = {
    0.0044330481f, 0.0540055826f, 0.2420362294f, 0.3990502730f,
    0.2420362294f, 0.0540055826f, 0.0044330481f
};

// ------------- prelude: zero image + twiddles + params + ctf transpose ------

__global__ void prelude_kernel(const float* __restrict__ rows,
                               const float* __restrict__ shifts,
                               const float* __restrict__ latent,
                               const float* __restrict__ W0, const float* __restrict__ b0,
                               const float* __restrict__ W1, const float* __restrict__ b1,
                               const float* __restrict__ W2, const float* __restrict__ b2,
                               const float* __restrict__ W3, const float* __restrict__ b3,
                               const float* __restrict__ ctf) {
    __shared__ float tt[32][33];
    int bid = blockIdx.x;
    int tid = threadIdx.x;
    if (bid >= ZERO_BLKS) {
        // ---- ctf transpose tile: [b][ky][kx] -> [b][kx][ky] ----
        int id  = bid - ZERO_BLKS;            // 0..639
        int bxk = id % 5;
        int byk = (id / 5) % 8;
        int b   = id / 40;
        int tx = tid & 31, ty = tid >> 5;
        int kx = bxk*32 + tx;
        #pragma unroll
        for (int j = 0; j < 4; j++) {
            int ky = byk*32 + ty + j*8;
            if (kx < HSPEC) tt[ty + j*8][tx] = ctf[((b << 8) + ky)*HSPEC + kx];
        }
        __syncthreads();
        #pragma unroll
        for (int j = 0; j < 4; j++) {
            int kxo = bxk*32 + ty + j*8;
            int kyo = byk*32 + tx;
            if (kxo < HSPEC) g_ctft[((b*HSPEC + kxo) << 8) + kyo] = tt[tx][ty + j*8];
        }
        return;
    }
    ((float4*)g_img)[bid*256 + tid] = make_float4(0.f, 0.f, 0.f, 0.f);
    if (bid != 0) return;
    if (tid < 128) {
        double s, c;
        sincos(-3.14159265358979323846 * (double)tid / 128.0, &s, &c);
        g_tw[tid] = make_float2((float)c, (float)s);
    }
    int b = tid;
    if (b >= BB) return;
    // ---- FROZEN position-path arithmetic (do not modify) ----
    float rot  = rows[b*3+0];
    float tilt = rows[b*3+1];
    float psi  = rows[b*3+2];
    float ca = cosf(rot),  sa = sinf(rot);
    float cb = cosf(tilt), sb = sinf(tilt);
    float cg = cosf(psi),  sg = sinf(psi);
    float cgcb = __fmul_rn(cg, cb);
    float sgcb = __fmul_rn(sg, cb);
    g_params[b][0] = __fsub_rn(__fmul_rn(cgcb, ca), __fmul_rn(sg, sa));
    g_params[b][1] = __fadd_rn(__fmul_rn(cgcb, sa), __fmul_rn(sg, ca));
    g_params[b][2] = -__fmul_rn(cg, sb);
    g_params[b][3] = __fsub_rn(__fmul_rn(-sgcb, ca), __fmul_rn(cg, sa));
    g_params[b][4] = __fadd_rn(__fmul_rn(-sgcb, sa), __fmul_rn(cg, ca));
    g_params[b][5] = __fmul_rn(sg, sb);
    g_params[b][6] = shifts[b*2+0];
    g_params[b][7] = shifts[b*2+1];

    float h[LATD];
    #pragma unroll
    for (int j = 0; j < LATD; j++) {
        float z = b0[j];
        #pragma unroll
        for (int l = 0; l < LATD; l++) z += latent[b*LATD+l] * W0[l*LATD+j];
        h[j] = sinf(30.0f * z);
    }
    const float* Ws[3] = {W1, W2, W3};
    const float* bs[3] = {b1, b2, b3};
    for (int L = 0; L < 3; L++) {
        float t[LATD];
        #pragma unroll
        for (int j = 0; j < LATD; j++) {
            float z = bs[L][j];
            #pragma unroll
            for (int l = 0; l < LATD; l++) z += h[l] * Ws[L][l*LATD+j];
            t[j] = sinf(z);
        }
        #pragma unroll
        for (int j = 0; j < LATD; j++) h[j] += t[j];
    }
    #pragma unroll
    for (int j = 0; j < LATD; j++) g_params[b][8+j] = h[j];
}

// ---------------- scatter ----------------------------------------------------

__global__ void scatter_kernel(const float* __restrict__ coords,
                               const float* __restrict__ values,
                               const float* __restrict__ Wd,
                               const float* __restrict__ bd) {
    __shared__ float sp[BB][16];
    __shared__ float sc[768];
    int t = threadIdx.x;
    if (t < BB*16) ((float*)sp)[t] = ((const float*)g_params)[t];
    int base = blockIdx.x * 256 * 3;
    #pragma unroll
    for (int f = 0; f < 3; f++) {
        int g = base + t + f*256;
        sc[t + f*256] = (g < NPTS*3) ? coords[g] : 0.0f;
    }
    __syncthreads();

    int n = blockIdx.x * blockDim.x + t;
    if (n >= NPTS) return;

    float cx = sc[t*3+0];
    float cy = sc[t*3+1];
    float cz = sc[t*3+2];
    float v   = values[n];
    float bdn = bd[n];
    float wd[LATD];
    #pragma unroll
    for (int l = 0; l < LATD; l++) wd[l] = Wd[l*NPTS + n];

    #pragma unroll
    for (int b = 0; b < BB; b++) {
        // ---- FROZEN position-path arithmetic (do not modify) ----
        float x = __fmul_rn(sp[b][0], cx);
        x = __fmaf_rn(sp[b][1], cy, x);
        x = __fmaf_rn(sp[b][2], cz, x);
        float y = __fmul_rn(sp[b][3], cx);
        y = __fmaf_rn(sp[b][4], cy, y);
        y = __fmaf_rn(sp[b][5], cz, y);
        float fx = rintf(__fadd_rn(__fadd_rn(x, sp[b][6]), 128.0f));
        float fy = rintf(__fadd_rn(__fadd_rn(y, sp[b][7]), 128.0f));
        fx = fminf(fmaxf(fx, 0.0f), 255.0f);
        fy = fminf(fmaxf(fy, 0.0f), 255.0f);
        int ix = (int)fx;
        int iy = (int)fy;
        float dot = sp[b][8] * wd[0];
        #pragma unroll
        for (int l = 1; l < LATD; l++) dot += sp[b][8+l] * wd[l];
        float val = v + (dot + bdn);
        atomicAdd(&g_img[(b << 16) | (iy << 8) | ix], val);
    }
}

// ---- FFT256 as 16x16: FFT16 in registers, one skewed smem transpose --------
// n = n1 + 16 n2 (n1 = thread t), k = k2 + 16 k1.
// s(k) = ((k&3)<<2) | (k>>2)  (base-4 digit reversal of FFT16 output).

#define C16_1 0.92387953251128674f
#define S16_1 0.38268343236508978f
#define C16_2 0.70710678118654752f

__device__ __forceinline__ float2 cmulc(float2 a, float wx, float wy) {
    return make_float2(a.x*wx - a.y*wy, a.x*wy + a.y*wx);
}

template<bool INV>
__device__ __forceinline__ void bfly4(float2& a, float2& b, float2& c, float2& d) {
    float t0x=a.x+c.x, t0y=a.y+c.y;
    float t1x=a.x-c.x, t1y=a.y-c.y;
    float t2x=b.x+d.x, t2y=b.y+d.y;
    float t3x=b.x-d.x, t3y=b.y-d.y;
    a = make_float2(t0x+t2x, t0y+t2y);
    c = make_float2(t0x-t2x, t0y-t2y);
    if (!INV) { b = make_float2(t1x+t3y, t1y-t3x); d = make_float2(t1x-t3y, t1y+t3x); }
    else      { b = make_float2(t1x-t3y, t1y+t3x); d = make_float2(t1x+t3y, t1y-t3x); }
}

template<bool INV>
__device__ __forceinline__ void fft16(float2 v[16]) {
    const float sg = INV ? 1.0f : -1.0f;
    bfly4<INV>(v[0], v[4], v[8],  v[12]);
    bfly4<INV>(v[1], v[5], v[9],  v[13]);
    bfly4<INV>(v[2], v[6], v[10], v[14]);
    bfly4<INV>(v[3], v[7], v[11], v[15]);
    v[5]  = cmulc(v[5],  C16_1,  sg*S16_1);
    v[9]  = cmulc(v[9],  C16_2,  sg*C16_2);
    v[6]  = cmulc(v[6],  C16_2,  sg*C16_2);
    v[13] = cmulc(v[13], S16_1,  sg*C16_1);
    v[7]  = cmulc(v[7],  S16_1,  sg*C16_1);
    v[10] = INV ? make_float2(-v[10].y, v[10].x)
                : make_float2( v[10].y, -v[10].x);
    v[14] = cmulc(v[14], -C16_2,  sg*C16_2);
    v[11] = cmulc(v[11], -C16_2,  sg*C16_2);
    v[15] = cmulc(v[15], -C16_1, -sg*S16_1);
    bfly4<INV>(v[0],  v[1],  v[2],  v[3]);
    bfly4<INV>(v[4],  v[5],  v[6],  v[7]);
    bfly4<INV>(v[8],  v[9],  v[10], v[11]);
    bfly4<INV>(v[12], v[13], v[14], v[15]);
}

#define SLOT(k) ((((k) & 3) << 2) | ((k) >> 2))

template<bool INV>
__device__ __forceinline__ void fft256_regs(float2 v[16], int t,
                                            float* trR, float* trI,
                                            const float2* stw) {
    fft16<INV>(v);
    #pragma unroll
    for (int k2 = 0; k2 < 16; k2++) {
        float2 a = v[SLOT(k2)];
        int e = t * k2;
        float2 w = stw[e & 127];
        if (e & 128) { w.x = -w.x; w.y = -w.y; }
        if (INV) w.y = -w.y;
        float2 p = make_float2(a.x*w.x - a.y*w.y, a.x*w.y + a.y*w.x);
        trR[t*17 + k2] = p.x;
        trI[t*17 + k2] = p.y;
    }
    __syncthreads();
    #pragma unroll
    for (int n1 = 0; n1 < 16; n1++)
        v[n1] = make_float2(trR[n1*17 + t], trI[n1*17 + t]);
    __syncthreads();
    fft16<INV>(v);
    // X[t + 16 k1] at v[SLOT(k1)]
}

// fused y-blur + x-blur + two-for-one forward row rFFT.
// Block: 64 threads = 4 FFTs = 4 row pairs = 8 rows of one image; grid 512.
__global__ void __launch_bounds__(64) fftrow_kernel() {
    __shared__ union {
        float  win[14][XSZ];                 // 14 KB (stage window)
        float  tr[2][4][272];                // 8.7 KB (FFT transpose)
        float2 st[HSPEC][9];                 // 9.3 KB (spectrum out-tile)
    } ua;
    __shared__ union {
        float yb[8][XSZ];                    // 8 KB (y-blurred rows)
        float zb[2][4][264];                 // 8.4 KB (Hermitian split buf)
    } ub;
    __shared__ float2 stw[128];
    int tid = threadIdx.x;
    int f = tid >> 4, t = tid & 15;
    stw[tid] = g_tw[tid];
    stw[tid + 64] = g_tw[tid + 64];
    int b  = blockIdx.x >> 5;
    int y0 = (blockIdx.x & 31) << 3;
    const float* imgb = g_img + (b << 16);
    // stage window rows y0-3 .. y0+10 (coalesced float4)
    for (int idx = tid; idx < 14*64; idx += 64) {
        int r = idx >> 6, x4 = idx & 63;
        int wr = y0 - 3 + r;
        if (wr >= 0 && wr < XSZ)
            ((float4*)ua.win[r])[x4] = ((const float4*)(imgb + (wr << 8)))[x4];
    }
    __syncthreads();
    // y-blur rows y0..y0+7 from window (guards/order match reference)
    for (int idx = tid; idx < 8*256; idx += 64) {
        int r = idx >> 8, c = idx & 255;
        int yg = y0 + r;
        float acc = 0.f;
        #pragma unroll
        for (int d = -3; d <= 3; d++) {
            int ya = yg + d;
            if (ya >= 0 && ya < XSZ) acc += c_gk[d+3] * ua.win[r + d + 3][c];
        }
        ub.yb[r][c] = acc;
    }
    __syncthreads();
    // x-blur straight into FFT input registers (pair rows 2f, 2f+1)
    float2 v[16];
    #pragma unroll
    for (int n2 = 0; n2 < 16; n2++) {
        int c = t + (n2 << 4);
        float a0 = 0.f, a1 = 0.f;
        #pragma unroll
        for (int d = -3; d <= 3; d++) {
            int cc = c + d;
            if (cc >= 0 && cc < XSZ) {
                a0 += c_gk[d+3] * ub.yb[2*f][cc];
                a1 += c_gk[d+3] * ub.yb[2*f+1][cc];
            }
        }
        v[n2] = make_float2(a0, a1);
    }
    __syncthreads();                         // x-blur reads done (win/yb die)
    fft256_regs<false>(v, t, ua.tr[0][f], ua.tr[1][f], stw);
    // scatter full z to zbuf (skewed) for the Hermitian split
    #pragma unroll
    for (int k1 = 0; k1 < 16; k1++) {
        int k = t + (k1 << 4);
        int a = k + (k >> 5);
        ub.zb[0][f][a] = v[SLOT(k1)].x;
        ub.zb[1][f][a] = v[SLOT(k1)].y;
    }
    __syncthreads();
    // split packed spectrum: Fa -> row 2f, Fb -> row 2f+1 (into st tile)
    for (int k = t; k <= 128; k += 16) {
        int kn = (256 - k) & 255;
        int ak = k + (k >> 5), an = kn + (kn >> 5);
        float zr = ub.zb[0][f][ak], zi = ub.zb[1][f][ak];
        float nr = ub.zb[0][f][an], ni = ub.zb[1][f][an];
        ua.st[k][2*f + 0] = make_float2(0.5f*(zr + nr), 0.5f*(zi - ni));
        ua.st[k][2*f + 1] = make_float2(0.5f*(zi + ni), 0.5f*(nr - zr));
    }
    __syncthreads();
    // coalesced write-out to [b][kx][y]
    for (int idx = tid; idx < HSPEC*8; idx += 64) {
        int k = idx >> 3, yl = idx & 7;
        g_spec[((b*HSPEC + k) << 8) + y0 + yl] = ua.st[k][yl];
    }
}

// forward y FFT, ctf multiply, inverse y FFT — all in registers, direct
// coalesced global loads/stores. Block: 128 threads = 8 kx columns.
__global__ void __launch_bounds__(128) fftcol_kernel() {
    __shared__ float tr[2][8][272];
    __shared__ float2 stw[128];
    int tid = threadIdx.x;
    int f = tid >> 4, t = tid & 15;
    stw[tid] = g_tw[tid];
    __syncthreads();
    int b   = blockIdx.x / 17;
    int kxr = (blockIdx.x % 17) * 8 + f;
    bool act = (kxr <= 128);
    int kx  = act ? kxr : 128;
    int base = (b*HSPEC + kx) << 8;
    float2 v[16];
    #pragma unroll
    for (int n2 = 0; n2 < 16; n2++) v[n2] = g_spec[base + t + (n2 << 4)];
    fft256_regs<false>(v, t, tr[0][f], tr[1][f], stw);
    float2 w[16];
    #pragma unroll
    for (int j = 0; j < 16; j++) {
        float c = g_ctft[base + t + (j << 4)];
        w[j] = make_float2(v[SLOT(j)].x * c, v[SLOT(j)].y * c);
    }
    fft256_regs<true>(w, t, tr[0][f], tr[1][f], stw);
    if (act) {
        #pragma unroll
        for (int m = 0; m < 16; m++)
            g_spec[base + t + (m << 4)] = w[SLOT(m)];
    }
}

// two-for-one inverse row rFFT with staged coalesced tile loads.
// irfft drops Im(h[0]) and Im(h[128]) — zero them before the packed merge.
// Block: 64 threads = 4 FFTs = 4 row pairs = 8 rows; grid 512.
__global__ void __launch_bounds__(64) ifftrow_kernel(float* __restrict__ out) {
    __shared__ float2 st[HSPEC][9];          // padded: conflict-free column reads
    __shared__ float  tr[2][4][272];
    __shared__ float2 stw[128];
    int tid = threadIdx.x;
    int f = tid >> 4, t = tid & 15;
    stw[tid] = g_tw[tid];
    stw[tid + 64] = g_tw[tid + 64];
    int b  = blockIdx.x >> 5;
    int y0 = (blockIdx.x & 31) << 3;
    // staged coalesced load of the 129 x 8 tile from [b][kx][y]
    for (int idx = tid; idx < HSPEC*8; idx += 64) {
        int k = idx >> 3, yl = idx & 7;
        st[k][yl] = g_spec[((b*HSPEC + k) << 8) + y0 + yl];
    }
    __syncthreads();
    float2 v[16];
    #pragma unroll
    for (int n2 = 0; n2 < 16; n2++) {
        int k = t + (n2 << 4);
        if (k <= 128) {
            float2 A  = st[k][2*f + 0];
            float2 Bv = st[k][2*f + 1];
            if (k == 0 || k == 128) { A.y = 0.f; Bv.y = 0.f; }  // irfft semantics
            v[n2] = make_float2(A.x - Bv.y, A.y + Bv.x);        // z = Fa + i Fb
        } else {
            int kp = 256 - k;
            float2 A  = st[kp][2*f + 0];
            float2 Bv = st[kp][2*f + 1];
            v[n2] = make_float2(A.x + Bv.y, -A.y + Bv.x);       // conj extension
        }
    }
    fft256_regs<true>(v, t, tr[0][f], tr[1][f], stw);
    const float sc = 1.0f / 65536.0f;
    int r0 = y0 + 2*f;
    float* o0 = out + (((b << 8) | r0) << 8);
    float* o1 = o0 + XSZ;
    #pragma unroll
    for (int m = 0; m < 16; m++) {
        int c = t + (m << 4);
        o0[c] = v[SLOT(m)].x * sc;
        o1[c] = v[SLOT(m)].y * sc;
    }
}

// ---------------- launch -----------------------------------------------------

extern "C" void kernel_launch(void* const* d_in, const int* in_sizes, int n_in,
                              void* d_out, int out_size) {
    const float* rows   = (const float*)d_in[0];
    const float* shifts = (const float*)d_in[1];
    const float* latent = (const float*)d_in[2];
    const float* coords = (const float*)d_in[3];
    const float* values = (const float*)d_in[4];
    const float* W0 = (const float*)d_in[5];
    const float* b0 = (const float*)d_in[6];
    const float* W1 = (const float*)d_in[7];
    const float* b1 = (const float*)d_in[8];
    const float* W2 = (const float*)d_in[9];
    const float* b2 = (const float*)d_in[10];
    const float* W3 = (const float*)d_in[11];
    const float* b3 = (const float*)d_in[12];
    const float* Wd = (const float*)d_in[13];
    const float* bd = (const float*)d_in[14];
    const float* ctf = (const float*)d_in[15];
    float* out = (float*)d_out;

    prelude_kernel<<<ZERO_BLKS + 640, 256>>>(rows, shifts, latent,
                                             W0, b0, W1, b1, W2, b2, W3, b3, ctf);
    scatter_kernel<<<(NPTS + 255)/256, 256>>>(coords, values, Wd, bd);
    fftrow_kernel<<<BB*32, 64>>>();
    fftcol_kernel<<<BB*17, 128>>>();
    ifftrow_kernel<<<BB*32, 64>>>(out);
}

// round 11
// speedup vs baseline: 1.2873x; 1.2873x over previous
#include <cuda_runtime.h>
#include <math.h>

#define BB 16
#define LATD 8
#define NPTS 500000
#define XSZ 256
#define HSPEC 129   // XSZ/2 + 1
#define IMG_ELEMS (BB*XSZ*XSZ)

// ---------------- scratch (device globals; no allocation allowed) ----------
__device__ float  g_img[IMG_ELEMS];                  // 4 MB accumulation image
__device__ float2 g_spec[BB*HSPEC*XSZ];              // spectrum, layout [b][kx][y]
__device__ float  g_ctft[BB*HSPEC*XSZ];              // ctf transposed [b][kx][ky]
__device__ float  g_params[BB][16];                  // R rows(6), shifts(2), h(8)
__device__ float2 g_tw[128];                         // exp(-2*pi*i*k/256)

// Gaussian kernel (sigma=1, radius=3), normalized (double-derived constants)
__device__ __constant__ float c_gk[7] = {
    0.0044330481f, 0.0540055826f, 0.2420362294f, 0.3990502730f,
    0.2420362294f, 0.0540055826f, 0.0044330481f
};

// ---------------- zero + prep (merged) --------------------------------------

__global__ void zero_prep_kernel(const float* __restrict__ rows,
                                 const float* __restrict__ shifts,
                                 const float* __restrict__ latent,
                                 const float* __restrict__ W0, const float* __restrict__ b0,
                                 const float* __restrict__ W1, const float* __restrict__ b1,
                                 const float* __restrict__ W2, const float* __restrict__ b2,
                                 const float* __restrict__ W3, const float* __restrict__ b3) {
    int i = blockIdx.x * blockDim.x + threadIdx.x;
    ((float4*)g_img)[i] = make_float4(0.f, 0.f, 0.f, 0.f);
    if (blockIdx.x != 0) return;
    int tid = threadIdx.x;
    if (tid < 128) {
        double s, c;
        sincos(-3.14159265358979323846 * (double)tid / 128.0, &s, &c);
        g_tw[tid] = make_float2((float)c, (float)s);
    }
    int b = tid;
    if (b >= BB) return;
    // ---- FROZEN position-path arithmetic (do not modify) ----
    float rot  = rows[b*3+0];
    float tilt = rows[b*3+1];
    float psi  = rows[b*3+2];
    float ca = cosf(rot),  sa = sinf(rot);
    float cb = cosf(tilt), sb = sinf(tilt);
    float cg = cosf(psi),  sg = sinf(psi);
    float cgcb = __fmul_rn(cg, cb);
    float sgcb = __fmul_rn(sg, cb);
    g_params[b][0] = __fsub_rn(__fmul_rn(cgcb, ca), __fmul_rn(sg, sa));
    g_params[b][1] = __fadd_rn(__fmul_rn(cgcb, sa), __fmul_rn(sg, ca));
    g_params[b][2] = -__fmul_rn(cg, sb);
    g_params[b][3] = __fsub_rn(__fmul_rn(-sgcb, ca), __fmul_rn(cg, sa));
    g_params[b][4] = __fadd_rn(__fmul_rn(-sgcb, sa), __fmul_rn(cg, ca));
    g_params[b][5] = __fmul_rn(sg, sb);
    g_params[b][6] = shifts[b*2+0];
    g_params[b][7] = shifts[b*2+1];

    float h[LATD];
    #pragma unroll
    for (int j = 0; j < LATD; j++) {
        float z = b0[j];
        #pragma unroll
        for (int l = 0; l < LATD; l++) z += latent[b*LATD+l] * W0[l*LATD+j];
        h[j] = sinf(30.0f * z);
    }
    const float* Ws[3] = {W1, W2, W3};
    const float* bs[3] = {b1, b2, b3};
    for (int L = 0; L < 3; L++) {
        float t[LATD];
        #pragma unroll
        for (int j = 0; j < LATD; j++) {
            float z = bs[L][j];
            #pragma unroll
            for (int l = 0; l < LATD; l++) z += h[l] * Ws[L][l*LATD+j];
            t[j] = sinf(z);
        }
        #pragma unroll
        for (int j = 0; j < LATD; j++) h[j] += t[j];
    }
    #pragma unroll
    for (int j = 0; j < LATD; j++) g_params[b][8+j] = h[j];
}

// ---------------- ctf transpose: [b][ky][kx] -> [b][kx][ky] -----------------

__global__ void ctft_kernel(const float* __restrict__ ctf) {
    __shared__ float t[32][33];
    int tx = threadIdx.x, ty = threadIdx.y;
    int bxk = blockIdx.x;        // kx tile (0..4)
    int byk = blockIdx.y;        // ky tile (0..7)
    int b   = blockIdx.z;
    int kx = bxk*32 + tx;
    #pragma unroll
    for (int j = 0; j < 4; j++) {
        int ky = byk*32 + ty + j*8;
        if (kx < HSPEC) t[ty + j*8][tx] = ctf[((b << 8) + ky)*HSPEC + kx];
    }
    __syncthreads();
    #pragma unroll
    for (int j = 0; j < 4; j++) {
        int kxo = bxk*32 + ty + j*8;
        int kyo = byk*32 + tx;
        if (kxo < HSPEC) g_ctft[((b*HSPEC + kxo) << 8) + kyo] = t[tx][ty + j*8];
    }
}

// ---------------- scatter ----------------------------------------------------

__global__ void scatter_kernel(const float* __restrict__ coords,
                               const float* __restrict__ values,
                               const float* __restrict__ Wd,
                               const float* __restrict__ bd) {
    __shared__ float sp[BB][16];
    __shared__ float sc[768];
    int t = threadIdx.x;
    if (t < BB*16) ((float*)sp)[t] = ((const float*)g_params)[t];
    int base = blockIdx.x * 256 * 3;
    #pragma unroll
    for (int f = 0; f < 3; f++) {
        int g = base + t + f*256;
        sc[t + f*256] = (g < NPTS*3) ? coords[g] : 0.0f;
    }
    __syncthreads();

    int n = blockIdx.x * blockDim.x + t;
    if (n >= NPTS) return;

    float cx = sc[t*3+0];
    float cy = sc[t*3+1];
    float cz = sc[t*3+2];
    float v   = values[n];
    float bdn = bd[n];
    float wd[LATD];
    #pragma unroll
    for (int l = 0; l < LATD; l++) wd[l] = Wd[l*NPTS + n];

    #pragma unroll
    for (int b = 0; b < BB; b++) {
        // ---- FROZEN position-path arithmetic (do not modify) ----
        float x = __fmul_rn(sp[b][0], cx);
        x = __fmaf_rn(sp[b][1], cy, x);
        x = __fmaf_rn(sp[b][2], cz, x);
        float y = __fmul_rn(sp[b][3], cx);
        y = __fmaf_rn(sp[b][4], cy, y);
        y = __fmaf_rn(sp[b][5], cz, y);
        float fx = rintf(__fadd_rn(__fadd_rn(x, sp[b][6]), 128.0f));
        float fy = rintf(__fadd_rn(__fadd_rn(y, sp[b][7]), 128.0f));
        fx = fminf(fmaxf(fx, 0.0f), 255.0f);
        fy = fminf(fmaxf(fy, 0.0f), 255.0f);
        int ix = (int)fx;
        int iy = (int)fy;
        float dot = sp[b][8] * wd[0];
        #pragma unroll
        for (int l = 1; l < LATD; l++) dot += sp[b][8+l] * wd[l];
        float val = v + (dot + bdn);
        atomicAdd(&g_img[(b << 16) | (iy << 8) | ix], val);
    }
}

// ---- FFT256 as 16x16: FFT16 in registers, one skewed smem transpose --------
// n = n1 + 16 n2 (n1 = thread t), k = k2 + 16 k1.
// s(k) = ((k&3)<<2) | (k>>2)  (base-4 digit reversal of FFT16 output).

#define C16_1 0.92387953251128674f
#define S16_1 0.38268343236508978f
#define C16_2 0.70710678118654752f

__device__ __forceinline__ float2 cmulc(float2 a, float wx, float wy) {
    return make_float2(a.x*wx - a.y*wy, a.x*wy + a.y*wx);
}

template<bool INV>
__device__ __forceinline__ void bfly4(float2& a, float2& b, float2& c, float2& d) {
    float t0x=a.x+c.x, t0y=a.y+c.y;
    float t1x=a.x-c.x, t1y=a.y-c.y;
    float t2x=b.x+d.x, t2y=b.y+d.y;
    float t3x=b.x-d.x, t3y=b.y-d.y;
    a = make_float2(t0x+t2x, t0y+t2y);
    c = make_float2(t0x-t2x, t0y-t2y);
    if (!INV) { b = make_float2(t1x+t3y, t1y-t3x); d = make_float2(t1x-t3y, t1y+t3x); }
    else      { b = make_float2(t1x-t3y, t1y+t3x); d = make_float2(t1x+t3y, t1y-t3x); }
}

template<bool INV>
__device__ __forceinline__ void fft16(float2 v[16]) {
    const float sg = INV ? 1.0f : -1.0f;
    bfly4<INV>(v[0], v[4], v[8],  v[12]);
    bfly4<INV>(v[1], v[5], v[9],  v[13]);
    bfly4<INV>(v[2], v[6], v[10], v[14]);
    bfly4<INV>(v[3], v[7], v[11], v[15]);
    v[5]  = cmulc(v[5],  C16_1,  sg*S16_1);
    v[9]  = cmulc(v[9],  C16_2,  sg*C16_2);
    v[6]  = cmulc(v[6],  C16_2,  sg*C16_2);
    v[13] = cmulc(v[13], S16_1,  sg*C16_1);
    v[7]  = cmulc(v[7],  S16_1,  sg*C16_1);
    v[10] = INV ? make_float2(-v[10].y, v[10].x)
                : make_float2( v[10].y, -v[10].x);
    v[14] = cmulc(v[14], -C16_2,  sg*C16_2);
    v[11] = cmulc(v[11], -C16_2,  sg*C16_2);
    v[15] = cmulc(v[15], -C16_1, -sg*S16_1);
    bfly4<INV>(v[0],  v[1],  v[2],  v[3]);
    bfly4<INV>(v[4],  v[5],  v[6],  v[7]);
    bfly4<INV>(v[8],  v[9],  v[10], v[11]);
    bfly4<INV>(v[12], v[13], v[14], v[15]);
}

#define SLOT(k) ((((k) & 3) << 2) | ((k) >> 2))

template<bool INV>
__device__ __forceinline__ void fft256_regs(float2 v[16], int t,
                                            float* trR, float* trI,
                                            const float2* stw) {
    fft16<INV>(v);
    #pragma unroll
    for (int k2 = 0; k2 < 16; k2++) {
        float2 a = v[SLOT(k2)];
        int e = t * k2;
        float2 w = stw[e & 127];
        if (e & 128) { w.x = -w.x; w.y = -w.y; }
        if (INV) w.y = -w.y;
        float2 p = make_float2(a.x*w.x - a.y*w.y, a.x*w.y + a.y*w.x);
        trR[t*17 + k2] = p.x;
        trI[t*17 + k2] = p.y;
    }
    __syncthreads();
    #pragma unroll
    for (int n1 = 0; n1 < 16; n1++)
        v[n1] = make_float2(trR[n1*17 + t], trI[n1*17 + t]);
    __syncthreads();
    fft16<INV>(v);
    // X[t + 16 k1] at v[SLOT(k1)]
}

// fused y-blur + x-blur + two-for-one forward row rFFT.
// Block: 128 threads = 8 FFTs = 8 row pairs = 16 rows of one image.
__global__ void __launch_bounds__(128) fftrow_kernel() {
    __shared__ union {
        float  win[22][XSZ];                 // 22.5 KB (stage window)
        float  tr[2][8][272];                // 17.4 KB (FFT transpose)
        float2 st[HSPEC][16];                // 16.5 KB (spectrum out-tile)
    } ua;
    __shared__ union {
        float yb[16][XSZ];                   // 16 KB (y-blurred rows)
        float zb[2][8][264];                 // 16.9 KB (Hermitian split buf)
    } ub;
    __shared__ float2 stw[128];
    int tid = threadIdx.x;
    int f = tid >> 4, t = tid & 15;
    stw[tid] = g_tw[tid];
    int b  = blockIdx.x >> 4;
    int y0 = (blockIdx.x & 15) << 4;
    const float* imgb = g_img + (b << 16);
    // stage window rows y0-3 .. y0+18 (coalesced float4)
    for (int idx = tid; idx < 22*64; idx += 128) {
        int r = idx >> 6, x4 = idx & 63;
        int wr = y0 - 3 + r;
        if (wr >= 0 && wr < XSZ)
            ((float4*)ua.win[r])[x4] = ((const float4*)(imgb + (wr << 8)))[x4];
    }
    __syncthreads();
    // y-blur rows y0..y0+15 from window (guards/order match reference)
    for (int idx = tid; idx < 16*256; idx += 128) {
        int r = idx >> 8, c = idx & 255;
        int yg = y0 + r;
        float acc = 0.f;
        #pragma unroll
        for (int d = -3; d <= 3; d++) {
            int ya = yg + d;
            if (ya >= 0 && ya < XSZ) acc += c_gk[d+3] * ua.win[r + d + 3][c];
        }
        ub.yb[r][c] = acc;
    }
    __syncthreads();
    // x-blur straight into FFT input registers (pair rows 2f, 2f+1)
    float2 v[16];
    #pragma unroll
    for (int n2 = 0; n2 < 16; n2++) {
        int c = t + (n2 << 4);
        float a0 = 0.f, a1 = 0.f;
        #pragma unroll
        for (int d = -3; d <= 3; d++) {
            int cc = c + d;
            if (cc >= 0 && cc < XSZ) {
                a0 += c_gk[d+3] * ub.yb[2*f][cc];
                a1 += c_gk[d+3] * ub.yb[2*f+1][cc];
            }
        }
        v[n2] = make_float2(a0, a1);
    }
    __syncthreads();                         // all x-blur reads done (win/yb die)
    fft256_regs<false>(v, t, ua.tr[0][f], ua.tr[1][f], stw);
    // scatter full z to zbuf (skewed) for the Hermitian split
    #pragma unroll
    for (int k1 = 0; k1 < 16; k1++) {
        int k = t + (k1 << 4);
        int a = k + (k >> 5);
        ub.zb[0][f][a] = v[SLOT(k1)].x;
        ub.zb[1][f][a] = v[SLOT(k1)].y;
    }
    __syncthreads();
    // split packed spectrum: Fa -> row 2f, Fb -> row 2f+1 (into st tile)
    for (int k = t; k <= 128; k += 16) {
        int kn = (256 - k) & 255;
        int ak = k + (k >> 5), an = kn + (kn >> 5);
        float zr = ub.zb[0][f][ak], zi = ub.zb[1][f][ak];
        float nr = ub.zb[0][f][an], ni = ub.zb[1][f][an];
        ua.st[k][2*f + 0] = make_float2(0.5f*(zr + nr), 0.5f*(zi - ni));
        ua.st[k][2*f + 1] = make_float2(0.5f*(zi + ni), 0.5f*(nr - zr));
    }
    __syncthreads();
    // coalesced write-out to [b][kx][y]
    for (int idx = tid; idx < HSPEC*16; idx += 128) {
        int k = idx >> 4, yl = idx & 15;
        g_spec[((b*HSPEC + k) << 8) + y0 + yl] = ua.st[k][yl];
    }
}

// forward y FFT, ctf multiply, inverse y FFT — all in registers, direct
// coalesced global loads/stores. Block: 128 threads = 8 kx columns.
__global__ void __launch_bounds__(128) fftcol_kernel() {
    __shared__ float tr[2][8][272];
    __shared__ float2 stw[128];
    int tid = threadIdx.x;
    int f = tid >> 4, t = tid & 15;
    stw[tid] = g_tw[tid];
    __syncthreads();
    int b   = blockIdx.x / 17;
    int kxr = (blockIdx.x % 17) * 8 + f;
    bool act = (kxr <= 128);
    int kx  = act ? kxr : 128;
    int base = (b*HSPEC + kx) << 8;
    float2 v[16];
    #pragma unroll
    for (int n2 = 0; n2 < 16; n2++) v[n2] = g_spec[base + t + (n2 << 4)];
    fft256_regs<false>(v, t, tr[0][f], tr[1][f], stw);
    float2 w[16];
    #pragma unroll
    for (int j = 0; j < 16; j++) {
        float c = g_ctft[base + t + (j << 4)];
        w[j] = make_float2(v[SLOT(j)].x * c, v[SLOT(j)].y * c);
    }
    fft256_regs<true>(w, t, tr[0][f], tr[1][f], stw);
    if (act) {
        #pragma unroll
        for (int m = 0; m < 16; m++)
            g_spec[base + t + (m << 4)] = w[SLOT(m)];
    }
}

// two-for-one inverse row rFFT with STAGED coalesced tile loads (the one
// change vs the 78.3us config: R8 read g_spec strided 2KB here).
// irfft drops Im(h[0]) and Im(h[128]) — zero them before the packed merge.
// Block: 128 threads = 8 FFTs = 8 row pairs = 16 rows; grid 256.
__global__ void __launch_bounds__(128) ifftrow_kernel(float* __restrict__ out) {
    __shared__ float2 st[HSPEC][17];         // padded: conflict-free column reads
    __shared__ float  tr[2][8][272];
    __shared__ float2 stw[128];
    int tid = threadIdx.x;
    int f = tid >> 4, t = tid & 15;
    stw[tid] = g_tw[tid];
    int b  = blockIdx.x >> 4;
    int y0 = (blockIdx.x & 15) << 4;
    // staged coalesced load of the 129 x 16 tile from [b][kx][y]
    for (int idx = tid; idx < HSPEC*16; idx += 128) {
        int k = idx >> 4, yl = idx & 15;
        st[k][yl] = g_spec[((b*HSPEC + k) << 8) + y0 + yl];
    }
    __syncthreads();
    float2 v[16];
    #pragma unroll
    for (int n2 = 0; n2 < 16; n2++) {
        int k = t + (n2 << 4);
        if (k <= 128) {
            float2 A  = st[k][2*f + 0];
            float2 Bv = st[k][2*f + 1];
            if (k == 0 || k == 128) { A.y = 0.f; Bv.y = 0.f; }  // irfft semantics
            v[n2] = make_float2(A.x - Bv.y, A.y + Bv.x);        // z = Fa + i Fb
        } else {
            int kp = 256 - k;
            float2 A  = st[kp][2*f + 0];
            float2 Bv = st[kp][2*f + 1];
            v[n2] = make_float2(A.x + Bv.y, -A.y + Bv.x);       // conj extension
        }
    }
    __syncthreads();                         // st reads done before tr reuse? (separate arrays, safe)
    fft256_regs<true>(v, t, tr[0][f], tr[1][f], stw);
    const float sc = 1.0f / 65536.0f;
    int r0 = y0 + 2*f;
    float* o0 = out + (((b << 8) | r0) << 8);
    float* o1 = o0 + XSZ;
    #pragma unroll
    for (int m = 0; m < 16; m++) {
        int c = t + (m << 4);
        o0[c] = v[SLOT(m)].x * sc;
        o1[c] = v[SLOT(m)].y * sc;
    }
}

// ---------------- launch -----------------------------------------------------

extern "C" void kernel_launch(void* const* d_in, const int* in_sizes, int n_in,
                              void* d_out, int out_size) {
    const float* rows   = (const float*)d_in[0];
    const float* shifts = (const float*)d_in[1];
    const float* latent = (const float*)d_in[2];
    const float* coords = (const float*)d_in[3];
    const float* values = (const float*)d_in[4];
    const float* W0 = (const float*)d_in[5];
    const float* b0 = (const float*)d_in[6];
    const float* W1 = (const float*)d_in[7];
    const float* b1 = (const float*)d_in[8];
    const float* W2 = (const float*)d_in[9];
    const float* b2 = (const float*)d_in[10];
    const float* W3 = (const float*)d_in[11];
    const float* b3 = (const float*)d_in[12];
    const float* Wd = (const float*)d_in[13];
    const float* bd = (const float*)d_in[14];
    const float* ctf = (const float*)d_in[15];
    float* out = (float*)d_out;

    zero_prep_kernel<<<IMG_ELEMS/4/256, 256>>>(rows, shifts, latent,
                                               W0, b0, W1, b1, W2, b2, W3, b3);
    ctft_kernel<<<dim3(5, 8, BB), dim3(32, 8)>>>(ctf);
    scatter_kernel<<<(NPTS + 255)/256, 256>>>(coords, values, Wd, bd);
    fftrow_kernel<<<BB*16, 128>>>();
    fftcol_kernel<<<BB*17, 128>>>();
    ifftrow_kernel<<<BB*16, 128>>>(out);
}

// round 12
// speedup vs baseline: 1.3633x; 1.0591x over previous
#include <cuda_runtime.h>
#include <math.h>

#define BB 16
#define LATD 8
#define NPTS 500000
#define XSZ 256
#define HSPEC 129   // XSZ/2 + 1
#define IMG_ELEMS (BB*XSZ*XSZ)

// ---------------- scratch (device globals; no allocation allowed) ----------
__device__ float  g_img[IMG_ELEMS];                  // 4 MB accumulation image
__device__ float2 g_spec[BB*XSZ*HSPEC];              // spectrum, layout [b][y][k]
__device__ float  g_params[BB][16];                  // R rows(6), shifts(2), h(8)
__device__ float2 g_tw[128];                         // exp(-2*pi*i*k/256)

// Gaussian kernel (sigma=1, radius=3), normalized (double-derived constants)
__device__ __constant__ float c_gk[7] = {
    0.0044330481f, 0.0540055826f, 0.2420362294f, 0.3990502730f,
    0.2420362294f, 0.0540055826f, 0.0044330481f
};

#define SKEW(i) ((i) + ((i) >> 5))   // bank-conflict skew for SoA smem

// ---------------- zero + prep (merged) --------------------------------------

__global__ void zero_prep_kernel(const float* __restrict__ rows,
                                 const float* __restrict__ shifts,
                                 const float* __restrict__ latent,
                                 const float* __restrict__ W0, const float* __restrict__ b0,
                                 const float* __restrict__ W1, const float* __restrict__ b1,
                                 const float* __restrict__ W2, const float* __restrict__ b2,
                                 const float* __restrict__ W3, const float* __restrict__ b3) {
    int i = blockIdx.x * blockDim.x + threadIdx.x;
    ((float4*)g_img)[i] = make_float4(0.f, 0.f, 0.f, 0.f);
    if (blockIdx.x != 0) return;
    int tid = threadIdx.x;
    if (tid < 128) {
        double s, c;
        sincos(-3.14159265358979323846 * (double)tid / 128.0, &s, &c);
        g_tw[tid] = make_float2((float)c, (float)s);
    }
    int b = tid;
    if (b >= BB) return;
    // ---- FROZEN position-path arithmetic (do not modify) ----
    float rot  = rows[b*3+0];
    float tilt = rows[b*3+1];
    float psi  = rows[b*3+2];
    float ca = cosf(rot),  sa = sinf(rot);
    float cb = cosf(tilt), sb = sinf(tilt);
    float cg = cosf(psi),  sg = sinf(psi);
    float cgcb = __fmul_rn(cg, cb);
    float sgcb = __fmul_rn(sg, cb);
    g_params[b][0] = __fsub_rn(__fmul_rn(cgcb, ca), __fmul_rn(sg, sa));
    g_params[b][1] = __fadd_rn(__fmul_rn(cgcb, sa), __fmul_rn(sg, ca));
    g_params[b][2] = -__fmul_rn(cg, sb);
    g_params[b][3] = __fsub_rn(__fmul_rn(-sgcb, ca), __fmul_rn(cg, sa));
    g_params[b][4] = __fadd_rn(__fmul_rn(-sgcb, sa), __fmul_rn(cg, ca));
    g_params[b][5] = __fmul_rn(sg, sb);
    g_params[b][6] = shifts[b*2+0];
    g_params[b][7] = shifts[b*2+1];

    float h[LATD];
    #pragma unroll
    for (int j = 0; j < LATD; j++) {
        float z = b0[j];
        #pragma unroll
        for (int l = 0; l < LATD; l++) z += latent[b*LATD+l] * W0[l*LATD+j];
        h[j] = sinf(30.0f * z);
    }
    const float* Ws[3] = {W1, W2, W3};
    const float* bs[3] = {b1, b2, b3};
    for (int L = 0; L < 3; L++) {
        float t[LATD];
        #pragma unroll
        for (int j = 0; j < LATD; j++) {
            float z = bs[L][j];
            #pragma unroll
            for (int l = 0; l < LATD; l++) z += h[l] * Ws[L][l*LATD+j];
            t[j] = sinf(z);
        }
        #pragma unroll
        for (int j = 0; j < LATD; j++) h[j] += t[j];
    }
    #pragma unroll
    for (int j = 0; j < LATD; j++) g_params[b][8+j] = h[j];
}

// ---------------- scatter ----------------------------------------------------

__global__ void scatter_kernel(const float* __restrict__ coords,
                               const float* __restrict__ values,
                               const float* __restrict__ Wd,
                               const float* __restrict__ bd) {
    __shared__ float sp[BB][16];
    __shared__ float sc[768];
    int t = threadIdx.x;
    if (t < BB*16) ((float*)sp)[t] = ((const float*)g_params)[t];
    int base = blockIdx.x * 256 * 3;
    #pragma unroll
    for (int f = 0; f < 3; f++) {
        int g = base + t + f*256;
        sc[t + f*256] = (g < NPTS*3) ? coords[g] : 0.0f;
    }
    __syncthreads();

    int n = blockIdx.x * blockDim.x + t;
    if (n >= NPTS) return;

    float cx = sc[t*3+0];
    float cy = sc[t*3+1];
    float cz = sc[t*3+2];
    float v   = values[n];
    float bdn = bd[n];
    float wd[LATD];
    #pragma unroll
    for (int l = 0; l < LATD; l++) wd[l] = Wd[l*NPTS + n];

    #pragma unroll
    for (int b = 0; b < BB; b++) {
        // ---- FROZEN position-path arithmetic (do not modify) ----
        float x = __fmul_rn(sp[b][0], cx);
        x = __fmaf_rn(sp[b][1], cy, x);
        x = __fmaf_rn(sp[b][2], cz, x);
        float y = __fmul_rn(sp[b][3], cx);
        y = __fmaf_rn(sp[b][4], cy, y);
        y = __fmaf_rn(sp[b][5], cz, y);
        float fx = rintf(__fadd_rn(__fadd_rn(x, sp[b][6]), 128.0f));
        float fy = rintf(__fadd_rn(__fadd_rn(y, sp[b][7]), 128.0f));
        fx = fminf(fmaxf(fx, 0.0f), 255.0f);
        fy = fminf(fmaxf(fy, 0.0f), 255.0f);
        int ix = (int)fx;
        int iy = (int)fy;
        float dot = sp[b][8] * wd[0];
        #pragma unroll
        for (int l = 1; l < LATD; l++) dot += sp[b][8+l] * wd[l];
        float val = v + (dot + bdn);
        atomicAdd(&g_img[(b << 16) | (iy << 8) | ix], val);
    }
}

// ---- radix-4 Stockham FFT, N=256, 64 lanes per FFT, SoA smem + skew --------
// (used by fftrow / ifftrow — the measured-best row-kernel configuration)

template<bool INV>
__device__ __forceinline__ void fft_r4(float* RA, float* IA, float* RB, float* IB,
                                       const float2* tw, int lane) {
    float* sr = RA; float* si = IA; float* dr = RB; float* di = IB;
    #pragma unroll
    for (int st = 0; st < 4; st++) {
        const int Ns = 1 << (2*st);
        int k    = lane & (Ns - 1);
        int base = ((lane - k) << 2) + k;
        float2 w1 = tw[k << (6 - 2*st)];
        if (INV) w1.y = -w1.y;
        float w2r = w1.x*w1.x - w1.y*w1.y, w2i = 2.f*w1.x*w1.y;
        float w3r = w2r*w1.x - w2i*w1.y,  w3i = w2r*w1.y + w2i*w1.x;
        float ar  = sr[SKEW(lane)],       ai  = si[SKEW(lane)];
        float br_ = sr[SKEW(lane+64)],    bi  = si[SKEW(lane+64)];
        float cr  = sr[SKEW(lane+128)],   ci  = si[SKEW(lane+128)];
        float dr_ = sr[SKEW(lane+192)],   di_ = si[SKEW(lane+192)];
        float tbr = w1.x*br_ - w1.y*bi,   tbi = w1.x*bi  + w1.y*br_;
        float tcr = w2r*cr  - w2i*ci,     tci = w2r*ci  + w2i*cr;
        float tdr = w3r*dr_ - w3i*di_,    tdi = w3r*di_ + w3i*dr_;
        float t0r = ar + tcr,  t0i = ai + tci;
        float t1r = ar - tcr,  t1i = ai - tci;
        float t2r = tbr + tdr, t2i = tbi + tdi;
        float t3r = tbr - tdr, t3i = tbi - tdi;
        dr[SKEW(base)]      = t0r + t2r;  di[SKEW(base)]      = t0i + t2i;
        dr[SKEW(base+2*Ns)] = t0r - t2r;  di[SKEW(base+2*Ns)] = t0i - t2i;
        if (!INV) {
            dr[SKEW(base+Ns)]   = t1r + t3i;  di[SKEW(base+Ns)]   = t1i - t3r;
            dr[SKEW(base+3*Ns)] = t1r - t3i;  di[SKEW(base+3*Ns)] = t1i + t3r;
        } else {
            dr[SKEW(base+Ns)]   = t1r - t3i;  di[SKEW(base+Ns)]   = t1i + t3r;
            dr[SKEW(base+3*Ns)] = t1r + t3i;  di[SKEW(base+3*Ns)] = t1i - t3r;
        }
        __syncthreads();
        float* tp;
        tp = sr; sr = dr; dr = tp;
        tp = si; si = di; di = tp;
    }
}

// fused y-blur + x-blur + two-for-one forward row rFFT (R6 measured 12.0us).
// Block: 256 threads = 4 FFTs = 4 row pairs; grid 512. Writes [b][y][k].
__global__ void fftrow_kernel() {
    __shared__ float RA[4][264], IA[4][264], RB[4][264], IB[4][264];
    __shared__ float2 tw[64];
    int tid = threadIdx.x, sub = tid >> 6, lane = tid & 63;
    if (tid < 64) tw[tid] = g_tw[tid];
    int rp = blockIdx.x * 4 + sub;        // pair index, 128 pairs per image
    int b  = rp >> 7;
    int y0 = (rp & 127) << 1;
    int y1 = y0 + 1;
    const float* imgb = g_img + (b << 16);
    for (int i = lane; i < XSZ; i += 64) {
        float a0 = 0.f, a1 = 0.f;
        #pragma unroll
        for (int d = -3; d <= 3; d++) {
            int ya = y0 + d;
            if (ya >= 0 && ya < XSZ) a0 += c_gk[d+3] * imgb[(ya << 8) + i];
            int yb = y1 + d;
            if (yb >= 0 && yb < XSZ) a1 += c_gk[d+3] * imgb[(yb << 8) + i];
        }
        RB[sub][i] = a0;
        IB[sub][i] = a1;
    }
    __syncthreads();
    for (int i = lane; i < XSZ; i += 64) {
        float a0 = 0.f, a1 = 0.f;
        #pragma unroll
        for (int d = -3; d <= 3; d++) {
            int xx = i + d;
            if (xx >= 0 && xx < XSZ) {
                a0 += c_gk[d+3] * RB[sub][xx];
                a1 += c_gk[d+3] * IB[sub][xx];
            }
        }
        RA[sub][SKEW(i)] = a0;
        IA[sub][SKEW(i)] = a1;
    }
    __syncthreads();
    fft_r4<false>(RA[sub], IA[sub], RB[sub], IB[sub], tw, lane);
    long base0 = (long)((b << 8) | y0) * HSPEC;
    long base1 = (long)((b << 8) | y1) * HSPEC;
    for (int k = lane; k <= 128; k += 64) {
        int kn = (256 - k) & 255;
        float zr = RA[sub][SKEW(k)],  zi = IA[sub][SKEW(k)];
        float nr = RA[sub][SKEW(kn)], ni = IA[sub][SKEW(kn)];
        g_spec[base0 + k] = make_float2(0.5f*(zr + nr), 0.5f*(zi - ni));
        g_spec[base1 + k] = make_float2(0.5f*(zi + ni), 0.5f*(nr - zr));
    }
}

// ---- FFT256 as 16x16 in registers (for fftcol) ------------------------------

#define C16_1 0.92387953251128674f
#define S16_1 0.38268343236508978f
#define C16_2 0.70710678118654752f

__device__ __forceinline__ float2 cmulc(float2 a, float wx, float wy) {
    return make_float2(a.x*wx - a.y*wy, a.x*wy + a.y*wx);
}

template<bool INV>
__device__ __forceinline__ void bfly4(float2& a, float2& b, float2& c, float2& d) {
    float t0x=a.x+c.x, t0y=a.y+c.y;
    float t1x=a.x-c.x, t1y=a.y-c.y;
    float t2x=b.x+d.x, t2y=b.y+d.y;
    float t3x=b.x-d.x, t3y=b.y-d.y;
    a = make_float2(t0x+t2x, t0y+t2y);
    c = make_float2(t0x-t2x, t0y-t2y);
    if (!INV) { b = make_float2(t1x+t3y, t1y-t3x); d = make_float2(t1x-t3y, t1y+t3x); }
    else      { b = make_float2(t1x-t3y, t1y+t3x); d = make_float2(t1x+t3y, t1y-t3x); }
}

template<bool INV>
__device__ __forceinline__ void fft16(float2 v[16]) {
    const float sg = INV ? 1.0f : -1.0f;
    bfly4<INV>(v[0], v[4], v[8],  v[12]);
    bfly4<INV>(v[1], v[5], v[9],  v[13]);
    bfly4<INV>(v[2], v[6], v[10], v[14]);
    bfly4<INV>(v[3], v[7], v[11], v[15]);
    v[5]  = cmulc(v[5],  C16_1,  sg*S16_1);
    v[9]  = cmulc(v[9],  C16_2,  sg*C16_2);
    v[6]  = cmulc(v[6],  C16_2,  sg*C16_2);
    v[13] = cmulc(v[13], S16_1,  sg*C16_1);
    v[7]  = cmulc(v[7],  S16_1,  sg*C16_1);
    v[10] = INV ? make_float2(-v[10].y, v[10].x)
                : make_float2( v[10].y, -v[10].x);
    v[14] = cmulc(v[14], -C16_2,  sg*C16_2);
    v[11] = cmulc(v[11], -C16_2,  sg*C16_2);
    v[15] = cmulc(v[15], -C16_1, -sg*S16_1);
    bfly4<INV>(v[0],  v[1],  v[2],  v[3]);
    bfly4<INV>(v[4],  v[5],  v[6],  v[7]);
    bfly4<INV>(v[8],  v[9],  v[10], v[11]);
    bfly4<INV>(v[12], v[13], v[14], v[15]);
}

#define SLOT(k) ((((k) & 3) << 2) | ((k) >> 2))

template<bool INV>
__device__ __forceinline__ void fft256_regs(float2 v[16], int t,
                                            float* trR, float* trI,
                                            const float2* stw) {
    fft16<INV>(v);
    #pragma unroll
    for (int k2 = 0; k2 < 16; k2++) {
        float2 a = v[SLOT(k2)];
        int e = t * k2;
        float2 w = stw[e & 127];
        if (e & 128) { w.x = -w.x; w.y = -w.y; }
        if (INV) w.y = -w.y;
        float2 p = make_float2(a.x*w.x - a.y*w.y, a.x*w.y + a.y*w.x);
        trR[t*17 + k2] = p.x;
        trI[t*17 + k2] = p.y;
    }
    __syncthreads();
    #pragma unroll
    for (int n1 = 0; n1 < 16; n1++)
        v[n1] = make_float2(trR[n1*17 + t], trI[n1*17 + t]);
    __syncthreads();
    fft16<INV>(v);
    // X[t + 16 k1] at v[SLOT(k1)]
}

// forward y FFT, ctf multiply, inverse y FFT — register FFT with smem-staged
// tiles bridging the [b][y][k] layout (this kernel absorbs the transpose AND
// the former ctft kernel). Block: 128 threads = 8 k-columns; grid BB*17.
__global__ void __launch_bounds__(128) fftcol_kernel(const float* __restrict__ ctf) {
    __shared__ float2 tin[XSZ][9];        // 18 KB   in/out tile (padded)
    __shared__ float  ctile[XSZ][9];      // 9.2 KB  ctf tile
    __shared__ float  tr[2][8][272];      // 17.4 KB FFT transpose
    __shared__ float2 stw[128];           // 1 KB
    int tid = threadIdx.x;
    int f = tid >> 4, t = tid & 15;
    stw[tid] = g_tw[tid];
    int b   = blockIdx.x / 17;
    int kx0 = (blockIdx.x % 17) * 8;
    // stage input spectrum + ctf tile (coalesced 64B/32B chunks per y-row)
    for (int idx = tid; idx < XSZ*8; idx += 128) {
        int y = idx >> 3, kxl = idx & 7;
        int kx = kx0 + kxl; if (kx > 128) kx = 128;
        long g = (long)((b << 8) + y) * HSPEC + kx;
        tin[y][kxl]   = g_spec[g];
        ctile[y][kxl] = ctf[g];
    }
    __syncthreads();
    float2 v[16];
    #pragma unroll
    for (int n2 = 0; n2 < 16; n2++) v[n2] = tin[t + (n2 << 4)][f];
    fft256_regs<false>(v, t, tr[0][f], tr[1][f], stw);
    float2 w[16];
    #pragma unroll
    for (int j = 0; j < 16; j++) {
        float c = ctile[t + (j << 4)][f];
        w[j] = make_float2(v[SLOT(j)].x * c, v[SLOT(j)].y * c);
    }
    fft256_regs<true>(w, t, tr[0][f], tr[1][f], stw);
    __syncthreads();                      // all tile reads complete
    #pragma unroll
    for (int m = 0; m < 16; m++) tin[t + (m << 4)][f] = w[SLOT(m)];
    __syncthreads();
    // coalesced write-back to [b][y][k]
    for (int idx = tid; idx < XSZ*8; idx += 128) {
        int y = idx >> 3, kxl = idx & 7;
        int kx = kx0 + kxl;
        if (kx <= 128)
            g_spec[(long)((b << 8) + y) * HSPEC + kx] = tin[y][kxl];
    }
}

// two-for-one inverse row rFFT (R6 configuration; [b][y][k] reads coalesced).
// irfft drops Im(h[0]) and Im(h[128]) — zero them before the packed merge.
__global__ void ifftrow_kernel(float* __restrict__ out) {
    __shared__ float RA[4][264], IA[4][264], RB[4][264], IB[4][264];
    __shared__ float2 tw[64];
    int tid = threadIdx.x, sub = tid >> 6, lane = tid & 63;
    if (tid < 64) tw[tid] = g_tw[tid];
    int rp = blockIdx.x * 4 + sub;
    int b  = rp >> 7;
    int y0 = (rp & 127) << 1;
    int y1 = y0 + 1;
    long base0 = (long)((b << 8) | y0) * HSPEC;
    long base1 = (long)((b << 8) | y1) * HSPEC;
    for (int k = lane; k <= 128; k += 64) {
        float2 A  = g_spec[base0 + k];
        float2 Bv = g_spec[base1 + k];
        if (k == 0 || k == 128) { A.y = 0.f; Bv.y = 0.f; }   // irfft semantics
        RA[sub][SKEW(k)] = A.x - Bv.y;     // z[k] = Fa[k] + i*Fb[k]
        IA[sub][SKEW(k)] = A.y + Bv.x;
        if (k >= 1 && k <= 127) {
            int m = 256 - k;               // z[m] = conj(Fa[k]) + i*conj(Fb[k])
            RA[sub][SKEW(m)] =  A.x + Bv.y;
            IA[sub][SKEW(m)] = -A.y + Bv.x;
        }
    }
    __syncthreads();
    fft_r4<true>(RA[sub], IA[sub], RB[sub], IB[sub], tw, lane);
    const float sc = 1.0f / 65536.0f;
    float* o0 = out + ((long)((b << 8) | y0) << 8);
    float* o1 = out + ((long)((b << 8) | y1) << 8);
    for (int i = lane; i < XSZ; i += 64) {
        o0[i] = RA[sub][SKEW(i)] * sc;
        o1[i] = IA[sub][SKEW(i)] * sc;
    }
}

// ---------------- launch -----------------------------------------------------

extern "C" void kernel_launch(void* const* d_in, const int* in_sizes, int n_in,
                              void* d_out, int out_size) {
    const float* rows   = (const float*)d_in[0];
    const float* shifts = (const float*)d_in[1];
    const float* latent = (const float*)d_in[2];
    const float* coords = (const float*)d_in[3];
    const float* values = (const float*)d_in[4];
    const float* W0 = (const float*)d_in[5];
    const float* b0 = (const float*)d_in[6];
    const float* W1 = (const float*)d_in[7];
    const float* b1 = (const float*)d_in[8];
    const float* W2 = (const float*)d_in[9];
    const float* b2 = (const float*)d_in[10];
    const float* W3 = (const float*)d_in[11];
    const float* b3 = (const float*)d_in[12];
    const float* Wd = (const float*)d_in[13];
    const float* bd = (const float*)d_in[14];
    const float* ctf = (const float*)d_in[15];
    float* out = (float*)d_out;

    zero_prep_kernel<<<IMG_ELEMS/4/256, 256>>>(rows, shifts, latent,
                                               W0, b0, W1, b1, W2, b2, W3, b3);
    scatter_kernel<<<(NPTS + 255)/256, 256>>>(coords, values, Wd, bd);
    fftrow_kernel<<<BB*XSZ/2/4, 256>>>();
    fftcol_kernel<<<BB*17, 128>>>(ctf);
    ifftrow_kernel<<<BB*XSZ/2/4, 256>>>(out);
}